// round 6
// baseline (speedup 1.0000x reference)
#include <cuda_runtime.h>
#include <math.h>

#define DIM      16
#define HID      128
#define NB       1024
#define NSTEPS   10
#define ROWS     18          // row 0: primal x, rows 1..16: tangents, row 17: primal x_star
#define NTHREADS 128
#define W4T_LD   132

struct Weights {
    const float* W0; const float* b0;
    const float* W1; const float* b1;
    const float* W2; const float* b2;
    const float* W3; const float* b3;
    const float* W4; const float* b4;
};

struct __align__(16) Smem {
    float Zin[ROWS][DIM];     // vel input (current)
    float H[2][ROWS][HID];    // hidden ping-pong
    float W4T[DIM][W4T_LD];   // transposed final-layer weights
    float Zfin[ROWS][DIM];    // final state for the solve
    float G[DIM][DIM + 1];    // Gram / Cholesky factor
    float gx[DIM];
    float diff[DIM];
    float wv[DIM];
    float u[DIM];
    float scal;               // 1/(||diff||+1e-8)
};

// ---- packed fp32x2 helpers ----
__device__ __forceinline__ void ffma2(unsigned long long& d,
                                      unsigned long long a,
                                      unsigned long long b) {
    asm("fma.rn.f32x2 %0, %1, %2, %0;" : "+l"(d) : "l"(a), "l"(b));
}
__device__ __forceinline__ unsigned long long pack2(float a, float b) {
    unsigned long long r;
    asm("mov.b64 %0, {%1, %2};" : "=l"(r) : "f"(a), "f"(b));
    return r;
}
__device__ __forceinline__ float red2(unsigned long long v) {
    float lo, hi;
    asm("mov.b64 {%0, %1}, %2;" : "=f"(lo), "=f"(hi) : "l"(v));
    return lo + hi;
}
__device__ __forceinline__ float htanh(float x) {
    float y;
    asm("tanh.approx.f32 %0, %1;" : "=f"(y) : "f"(x));
    return y;
}

// ---- hidden layer (128 -> 128), two 9-row passes to keep acc regs at 18 ----
__device__ __forceinline__ void hidden_layer(const float* __restrict__ W,
                                             const float* __restrict__ bb,
                                             const float (*Hin)[HID],
                                             float (*Hout)[HID], int j)
{
    float bj = __ldg(bb + j);
    unsigned long long binit = pack2(bj, 0.f);
    float g;

    // pass A: rows 0..8 (row 0 primal)
    {
        unsigned long long acc[9];
        acc[0] = binit;
        #pragma unroll
        for (int s = 1; s < 9; s++) acc[s] = 0ull;
        #pragma unroll 4
        for (int i = 0; i < HID; i += 4) {
            float w0 = __ldg(W + (i + 0) * HID + j);
            float w1 = __ldg(W + (i + 1) * HID + j);
            float w2 = __ldg(W + (i + 2) * HID + j);
            float w3 = __ldg(W + (i + 3) * HID + j);
            unsigned long long wa = pack2(w0, w1), wb = pack2(w2, w3);
            #pragma unroll
            for (int s = 0; s < 9; s++) {
                ulonglong2 hv = *reinterpret_cast<const ulonglong2*>(&Hin[s][i]);
                ffma2(acc[s], hv.x, wa);
                ffma2(acc[s], hv.y, wb);
            }
        }
        float h0 = htanh(red2(acc[0]));
        g = 1.f - h0 * h0;
        Hout[0][j] = h0;
        #pragma unroll
        for (int s = 1; s < 9; s++) Hout[s][j] = g * red2(acc[s]);
    }
    // pass B: rows 9..17 (row 17 primal)
    {
        unsigned long long acc[9];
        #pragma unroll
        for (int s = 0; s < 8; s++) acc[s] = 0ull;
        acc[8] = binit;
        #pragma unroll 4
        for (int i = 0; i < HID; i += 4) {
            float w0 = __ldg(W + (i + 0) * HID + j);
            float w1 = __ldg(W + (i + 1) * HID + j);
            float w2 = __ldg(W + (i + 2) * HID + j);
            float w3 = __ldg(W + (i + 3) * HID + j);
            unsigned long long wa = pack2(w0, w1), wb = pack2(w2, w3);
            #pragma unroll
            for (int s = 0; s < 9; s++) {
                ulonglong2 hv = *reinterpret_cast<const ulonglong2*>(&Hin[9 + s][i]);
                ffma2(acc[s], hv.x, wa);
                ffma2(acc[s], hv.y, wb);
            }
        }
        #pragma unroll
        for (int s = 0; s < 8; s++) Hout[9 + s][j] = g * red2(acc[s]);
        Hout[17][j] = htanh(red2(acc[8]));
    }
}

// ---- layer 0: 16 (+t) -> 128, same two-pass split ----
__device__ __forceinline__ void layer0(Smem& sm, float t, const Weights& w, int j)
{
    float bt = fmaf(t, __ldg(w.W0 + DIM * HID + j), __ldg(w.b0 + j));
    unsigned long long binit = pack2(bt, 0.f);
    float g;
    {
        unsigned long long acc[9];
        acc[0] = binit;
        #pragma unroll
        for (int s = 1; s < 9; s++) acc[s] = 0ull;
        #pragma unroll
        for (int i = 0; i < DIM; i += 4) {
            float w0 = __ldg(w.W0 + (i + 0) * HID + j);
            float w1 = __ldg(w.W0 + (i + 1) * HID + j);
            float w2 = __ldg(w.W0 + (i + 2) * HID + j);
            float w3 = __ldg(w.W0 + (i + 3) * HID + j);
            unsigned long long wa = pack2(w0, w1), wb = pack2(w2, w3);
            #pragma unroll
            for (int s = 0; s < 9; s++) {
                ulonglong2 hv = *reinterpret_cast<const ulonglong2*>(&sm.Zin[s][i]);
                ffma2(acc[s], hv.x, wa);
                ffma2(acc[s], hv.y, wb);
            }
        }
        float h0 = htanh(red2(acc[0]));
        g = 1.f - h0 * h0;
        sm.H[0][0][j] = h0;
        #pragma unroll
        for (int s = 1; s < 9; s++) sm.H[0][s][j] = g * red2(acc[s]);
    }
    {
        unsigned long long acc[9];
        #pragma unroll
        for (int s = 0; s < 8; s++) acc[s] = 0ull;
        acc[8] = binit;
        #pragma unroll
        for (int i = 0; i < DIM; i += 4) {
            float w0 = __ldg(w.W0 + (i + 0) * HID + j);
            float w1 = __ldg(w.W0 + (i + 1) * HID + j);
            float w2 = __ldg(w.W0 + (i + 2) * HID + j);
            float w3 = __ldg(w.W0 + (i + 3) * HID + j);
            unsigned long long wa = pack2(w0, w1), wb = pack2(w2, w3);
            #pragma unroll
            for (int s = 0; s < 9; s++) {
                ulonglong2 hv = *reinterpret_cast<const ulonglong2*>(&sm.Zin[9 + s][i]);
                ffma2(acc[s], hv.x, wa);
                ffma2(acc[s], hv.y, wb);
            }
        }
        #pragma unroll
        for (int s = 0; s < 8; s++) sm.H[0][9 + s][j] = g * red2(acc[s]);
        sm.H[0][17][j] = htanh(red2(acc[8]));
    }
}

__global__ __launch_bounds__(NTHREADS, 7) void flow_kernel(
    const float* __restrict__ x, const float* __restrict__ xs, Weights w,
    float* __restrict__ outp)
{
    __shared__ Smem sm;
    const int j = threadIdx.x;
    const int b = blockIdx.x;
    const int out_c = j & 15, rg = j >> 4;      // this thread owns (rows rg, rg+8, rg+16) x col out_c

    // stage transposed W4
    for (int e = j; e < DIM * HID; e += NTHREADS) {
        int o = e & 15, i = e >> 4;
        sm.W4T[o][i] = __ldg(w.W4 + e);
    }

    // per-thread RK4 state registers + initial Zin
    float zZ[3], zK[3];
    #pragma unroll
    for (int p = 0; p < 3; p++) {
        int row = rg + p * 8;
        float v = 0.f;
        if (row < ROWS) {
            if (row == 0)            v = x [b * DIM + out_c];
            else if (row == ROWS - 1) v = xs[b * DIM + out_c];
            else                     v = ((row - 1) == out_c) ? 1.f : 0.f;
            sm.Zin[row][out_c] = v;
        }
        zZ[p] = v; zK[p] = 0.f;
    }
    __syncthreads();

    const float dt = 1.f / NSTEPS;
    #pragma unroll 1
    for (int st = 0; st < 4 * NSTEPS; st++) {
        const int ph = st & 3;
        float t = (st >> 2) * dt;
        if (ph == 1 || ph == 2) t += 0.5f * dt;
        else if (ph == 3)       t += dt;

        layer0(sm, t, w, j);
        __syncthreads();
        hidden_layer(w.W1, w.b1, sm.H[0], sm.H[1], j); __syncthreads();
        hidden_layer(w.W2, w.b2, sm.H[1], sm.H[0], j); __syncthreads();
        hidden_layer(w.W3, w.b3, sm.H[0], sm.H[1], j); __syncthreads();

        // layer 4 (128 -> 16) fused with RK4 phase update; final hidden in H[1]
        #pragma unroll
        for (int p = 0; p < 3; p++) {
            int row = rg + p * 8;
            if (row < ROWS) {
                unsigned long long a0 = 0ull, a1 = 0ull;
                #pragma unroll 4
                for (int i = 0; i < HID; i += 4) {
                    ulonglong2 hv = *reinterpret_cast<const ulonglong2*>(&sm.H[1][row][i]);
                    ulonglong2 wv = *reinterpret_cast<const ulonglong2*>(&sm.W4T[out_c][i]);
                    ffma2(a0, hv.x, wv.x);
                    ffma2(a1, hv.y, wv.y);
                }
                float v = red2(a0) + red2(a1);
                if (row == 0 || row == ROWS - 1) v += __ldg(w.b4 + out_c);
                float zn;
                if (ph == 0)      { zK[p]  = v;        zn = zZ[p] + 0.5f * dt * v; }
                else if (ph == 1) { zK[p] += 2.f * v;  zn = zZ[p] + 0.5f * dt * v; }
                else if (ph == 2) { zK[p] += 2.f * v;  zn = zZ[p] + dt * v;        }
                else { zZ[p] = zZ[p] + (zK[p] + v) * (dt / 6.f); zn = zZ[p]; }
                sm.Zin[row][out_c] = zn;
            }
        }
        __syncthreads();
    }

    // ---- in-CTA solve: all of sample b's data is resident ----
    #pragma unroll
    for (int p = 0; p < 3; p++) {
        int row = rg + p * 8;
        if (row < ROWS) sm.Zfin[row][out_c] = zZ[p];
    }
    __syncthreads();

    if (j < DIM) sm.diff[j] = sm.Zfin[0][j] - sm.Zfin[17][j];
    __syncthreads();
    if (j == 0) {
        float ss = 0.f;
        #pragma unroll
        for (int i = 0; i < DIM; i++) ss += sm.diff[i] * sm.diff[i];
        sm.scal = 1.f / (sqrtf(ss) + 1e-8f);
    }
    __syncthreads();

    // G[jj][kk] = sum_i J[i][jj] J[i][kk],  J[i][c] = Zfin[c+1][i]
    for (int e = j; e < DIM * DIM; e += NTHREADS) {
        int jj = e & 15, kk = e >> 4;
        float s = 0.f;
        #pragma unroll
        for (int i = 0; i < DIM; i++) s += sm.Zfin[jj + 1][i] * sm.Zfin[kk + 1][i];
        if (jj == kk) s += 1e-6f;
        sm.G[jj][kk] = s;
    }
    if (j < DIM) {
        float s = 0.f;
        #pragma unroll
        for (int i = 0; i < DIM; i++) s += sm.Zfin[j + 1][i] * sm.diff[i];
        sm.gx[j] = s * sm.scal;
    }
    __syncthreads();

    // warp 0: Cholesky + triangular solves (column-parallel)
    if (j < 32) {
        const int lane = j;
        for (int c = 0; c < DIM; c++) {
            if (lane == c) {
                float d = sm.G[c][c];
                for (int k = 0; k < c; k++) d -= sm.G[c][k] * sm.G[c][k];
                sm.G[c][c] = sqrtf(fmaxf(d, 1e-30f));
            }
            __syncwarp();
            if (lane > c && lane < DIM) {
                float s = sm.G[lane][c];
                for (int k = 0; k < c; k++) s -= sm.G[lane][k] * sm.G[c][k];
                sm.G[lane][c] = s / sm.G[c][c];
            }
            __syncwarp();
        }
        if (lane < DIM) sm.wv[lane] = sm.gx[lane];
        __syncwarp();
        for (int c = 0; c < DIM; c++) {                 // L wv = gx
            if (lane == c) sm.wv[c] = sm.wv[c] / sm.G[c][c];
            __syncwarp();
            if (lane > c && lane < DIM) sm.wv[lane] -= sm.G[lane][c] * sm.wv[c];
            __syncwarp();
        }
        if (lane < DIM) sm.u[lane] = sm.wv[lane];
        __syncwarp();
        for (int c = DIM - 1; c >= 0; c--) {            // L^T u = wv
            if (lane == c) sm.u[c] = sm.u[c] / sm.G[c][c];
            __syncwarp();
            if (lane < c) sm.u[lane] -= sm.G[c][lane] * sm.u[c];
            __syncwarp();
        }
        if (lane < DIM) outp[b * DIM + lane] = -sm.u[lane];
    }
}

extern "C" void kernel_launch(void* const* d_in, const int* in_sizes, int n_in,
                              void* d_out, int out_size)
{
    Weights w;
    const float* x  = (const float*)d_in[0];
    const float* xs = (const float*)d_in[1];
    w.W0 = (const float*)d_in[2];  w.b0 = (const float*)d_in[3];
    w.W1 = (const float*)d_in[4];  w.b1 = (const float*)d_in[5];
    w.W2 = (const float*)d_in[6];  w.b2 = (const float*)d_in[7];
    w.W3 = (const float*)d_in[8];  w.b3 = (const float*)d_in[9];
    w.W4 = (const float*)d_in[10]; w.b4 = (const float*)d_in[11];
    float* out = (float*)d_out;

    flow_kernel<<<NB, NTHREADS>>>(x, xs, w, out);
}

// round 8
// speedup vs baseline: 1.1280x; 1.1280x over previous
#include <cuda_runtime.h>
#include <math.h>

#define DIM      16
#define HID      128
#define NB       1024
#define NSTEPS   10
#define ROWS     18          // row 0: primal x, rows 1..16: tangents, row 17: primal x_star
#define SPC      2           // samples per CTA
#define NTHREADS 128

struct Weights {
    const float* W0; const float* b0;
    const float* W1; const float* b1;
    const float* W2; const float* b2;
    const float* W3; const float* b3;
    const float* W4; const float* b4;
};

struct __align__(16) Smem {
    float Zin[SPC][ROWS][DIM];      // state / vel input (also final state)
    float H[SPC][2][ROWS][HID];     // hidden ping-pong per sample
    float G[SPC][DIM][DIM + 1];     // Gram / Cholesky
    float diff[SPC][DIM];
    float gx[SPC][DIM];
    float wv[SPC][DIM];
    float u[SPC][DIM];
    float scal[SPC];
};

// ---- packed fp32x2 helpers ----
__device__ __forceinline__ void ffma2(unsigned long long& d,
                                      unsigned long long a,
                                      unsigned long long b) {
    asm("fma.rn.f32x2 %0, %1, %2, %0;" : "+l"(d) : "l"(a), "l"(b));
}
__device__ __forceinline__ unsigned long long pack2(float a, float b) {
    unsigned long long r;
    asm("mov.b64 %0, {%1, %2};" : "=l"(r) : "f"(a), "f"(b));
    return r;
}
__device__ __forceinline__ float red2(unsigned long long v) {
    float lo, hi;
    asm("mov.b64 {%0, %1}, %2;" : "=f"(lo), "=f"(hi) : "l"(v));
    return lo + hi;
}
__device__ __forceinline__ float htanh(float x) {
    float y;
    asm("tanh.approx.f32 %0, %1;" : "=f"(y) : "f"(x));
    return y;
}

// ---- hidden layer 128->128: thread owns outputs {2j2, 2j2+1}, ALL 18 rows ----
__device__ __forceinline__ void hidden_layer(const float* __restrict__ W,
                                             const float* __restrict__ bb,
                                             const float (*Hin)[HID],
                                             float (*Hout)[HID], int j2)
{
    unsigned long long a0[ROWS], a1[ROWS];
    float2 bj = __ldg(reinterpret_cast<const float2*>(bb + 2 * j2));
    #pragma unroll
    for (int s = 0; s < ROWS; s++) { a0[s] = 0ull; a1[s] = 0ull; }
    a0[0]  = pack2(bj.x, 0.f); a1[0]  = pack2(bj.y, 0.f);
    a0[17] = pack2(bj.x, 0.f); a1[17] = pack2(bj.y, 0.f);

    const float* Wp = W + 2 * j2;
    // rotated pipeline: weights for i-group loaded one iteration ahead
    float2 p0 = __ldg(reinterpret_cast<const float2*>(Wp + 0 * HID));
    float2 p1 = __ldg(reinterpret_cast<const float2*>(Wp + 1 * HID));
    float2 p2 = __ldg(reinterpret_cast<const float2*>(Wp + 2 * HID));
    float2 p3 = __ldg(reinterpret_cast<const float2*>(Wp + 3 * HID));

    #pragma unroll 1
    for (int i = 0; i < HID; i += 4) {
        unsigned long long wa0 = pack2(p0.x, p1.x), wb0 = pack2(p2.x, p3.x);
        unsigned long long wa1 = pack2(p0.y, p1.y), wb1 = pack2(p2.y, p3.y);
        if (i + 4 < HID) {
            p0 = __ldg(reinterpret_cast<const float2*>(Wp + (i + 4) * HID));
            p1 = __ldg(reinterpret_cast<const float2*>(Wp + (i + 5) * HID));
            p2 = __ldg(reinterpret_cast<const float2*>(Wp + (i + 6) * HID));
            p3 = __ldg(reinterpret_cast<const float2*>(Wp + (i + 7) * HID));
        }
        #pragma unroll
        for (int s = 0; s < ROWS; s++) {
            ulonglong2 hv = *reinterpret_cast<const ulonglong2*>(&Hin[s][i]);
            ffma2(a0[s], hv.x, wa0); ffma2(a0[s], hv.y, wb0);
            ffma2(a1[s], hv.x, wa1); ffma2(a1[s], hv.y, wb1);
        }
    }

    float h00 = htanh(red2(a0[0])), h01 = htanh(red2(a1[0]));
    float g0 = 1.f - h00 * h00, g1 = 1.f - h01 * h01;
    Hout[0][2 * j2] = h00; Hout[0][2 * j2 + 1] = h01;
    #pragma unroll
    for (int s = 1; s < 17; s++) {
        Hout[s][2 * j2]     = g0 * red2(a0[s]);
        Hout[s][2 * j2 + 1] = g1 * red2(a1[s]);
    }
    Hout[17][2 * j2]     = htanh(red2(a0[17]));
    Hout[17][2 * j2 + 1] = htanh(red2(a1[17]));
}

// ---- layer 0: 16(+t) -> 128 ----
__device__ __forceinline__ void layer0(const float (*Zin)[DIM], float (*Hout)[HID],
                                       float t, const Weights& w, int j2)
{
    unsigned long long a0[ROWS], a1[ROWS];
    float2 bj = __ldg(reinterpret_cast<const float2*>(w.b0 + 2 * j2));
    float2 wt = __ldg(reinterpret_cast<const float2*>(w.W0 + DIM * HID + 2 * j2));
    float bt0 = fmaf(t, wt.x, bj.x), bt1 = fmaf(t, wt.y, bj.y);
    #pragma unroll
    for (int s = 0; s < ROWS; s++) { a0[s] = 0ull; a1[s] = 0ull; }
    a0[0]  = pack2(bt0, 0.f); a1[0]  = pack2(bt1, 0.f);
    a0[17] = pack2(bt0, 0.f); a1[17] = pack2(bt1, 0.f);

    const float* Wp = w.W0 + 2 * j2;
    #pragma unroll
    for (int i = 0; i < DIM; i += 4) {
        float2 p0 = __ldg(reinterpret_cast<const float2*>(Wp + (i + 0) * HID));
        float2 p1 = __ldg(reinterpret_cast<const float2*>(Wp + (i + 1) * HID));
        float2 p2 = __ldg(reinterpret_cast<const float2*>(Wp + (i + 2) * HID));
        float2 p3 = __ldg(reinterpret_cast<const float2*>(Wp + (i + 3) * HID));
        unsigned long long wa0 = pack2(p0.x, p1.x), wb0 = pack2(p2.x, p3.x);
        unsigned long long wa1 = pack2(p0.y, p1.y), wb1 = pack2(p2.y, p3.y);
        #pragma unroll
        for (int s = 0; s < ROWS; s++) {
            ulonglong2 hv = *reinterpret_cast<const ulonglong2*>(&Zin[s][i]);
            ffma2(a0[s], hv.x, wa0); ffma2(a0[s], hv.y, wb0);
            ffma2(a1[s], hv.x, wa1); ffma2(a1[s], hv.y, wb1);
        }
    }

    float h00 = htanh(red2(a0[0])), h01 = htanh(red2(a1[0]));
    float g0 = 1.f - h00 * h00, g1 = 1.f - h01 * h01;
    Hout[0][2 * j2] = h00; Hout[0][2 * j2 + 1] = h01;
    #pragma unroll
    for (int s = 1; s < 17; s++) {
        Hout[s][2 * j2]     = g0 * red2(a0[s]);
        Hout[s][2 * j2 + 1] = g1 * red2(a1[s]);
    }
    Hout[17][2 * j2]     = htanh(red2(a0[17]));
    Hout[17][2 * j2 + 1] = htanh(red2(a1[17]));
}

__global__ __launch_bounds__(NTHREADS, 4) void flow_kernel(
    const float* __restrict__ x, const float* __restrict__ xs, Weights w,
    float* __restrict__ outp)
{
    __shared__ Smem sm;
    const int tid = threadIdx.x;
    const int sh  = tid >> 6;          // sample within CTA
    const int j2  = tid & 63;          // output pair {2j2, 2j2+1}
    // L4/RK4 thread layout: (sh, out_c, rq) owns rows rq+4p (p<5, row<18)
    const int out_c = tid & 15, rq = (tid >> 4) & 3;

    // ---- init states ----
    for (int e = tid; e < SPC * ROWS * DIM; e += NTHREADS) {
        int ss = e / (ROWS * DIM), rr = (e / DIM) % ROWS, cc = e & 15;
        int s_idx = blockIdx.x * SPC + ss;
        float v;
        if (rr == 0)            v = x [s_idx * DIM + cc];
        else if (rr == ROWS - 1) v = xs[s_idx * DIM + cc];
        else                    v = ((rr - 1) == cc) ? 1.f : 0.f;
        sm.Zin[ss][rr][cc] = v;
    }
    __syncthreads();

    float zZ[5], zK[5];
    #pragma unroll
    for (int p = 0; p < 5; p++) {
        int row = rq + 4 * p;
        zZ[p] = (row < ROWS) ? sm.Zin[sh][row][out_c] : 0.f;
        zK[p] = 0.f;
    }

    const float dt = 1.f / NSTEPS;
    #pragma unroll 1
    for (int st = 0; st < 4 * NSTEPS; st++) {
        const int ph = st & 3;
        float t = (st >> 2) * dt;
        if (ph == 1 || ph == 2) t += 0.5f * dt;
        else if (ph == 3)       t += dt;

        layer0(sm.Zin[sh], sm.H[sh][0], t, w, j2);          __syncthreads();
        hidden_layer(w.W1, w.b1, sm.H[sh][0], sm.H[sh][1], j2); __syncthreads();
        hidden_layer(w.W2, w.b2, sm.H[sh][1], sm.H[sh][0], j2); __syncthreads();
        hidden_layer(w.W3, w.b3, sm.H[sh][0], sm.H[sh][1], j2); __syncthreads();

        // ---- layer 4 (128->16) fused with RK4 phase update; hidden in H[sh][1] ----
        {
            unsigned long long acc[5];
            #pragma unroll
            for (int p = 0; p < 5; p++) acc[p] = 0ull;
            const float* W4p = w.W4 + out_c;
            #pragma unroll 4
            for (int i = 0; i < HID; i += 4) {
                float w0 = __ldg(W4p + (i + 0) * DIM);
                float w1 = __ldg(W4p + (i + 1) * DIM);
                float w2 = __ldg(W4p + (i + 2) * DIM);
                float w3 = __ldg(W4p + (i + 3) * DIM);
                unsigned long long wa = pack2(w0, w1), wb = pack2(w2, w3);
                #pragma unroll
                for (int p = 0; p < 5; p++) {
                    int row = rq + 4 * p;
                    if (row < ROWS) {
                        ulonglong2 hv = *reinterpret_cast<const ulonglong2*>(&sm.H[sh][1][row][i]);
                        ffma2(acc[p], hv.x, wa);
                        ffma2(acc[p], hv.y, wb);
                    }
                }
            }
            float b4c = __ldg(w.b4 + out_c);
            #pragma unroll
            for (int p = 0; p < 5; p++) {
                int row = rq + 4 * p;
                if (row < ROWS) {
                    float v = red2(acc[p]);
                    if (row == 0 || row == ROWS - 1) v += b4c;
                    float zn;
                    if (ph == 0)      { zK[p]  = v;        zn = zZ[p] + 0.5f * dt * v; }
                    else if (ph == 1) { zK[p] += 2.f * v;  zn = zZ[p] + 0.5f * dt * v; }
                    else if (ph == 2) { zK[p] += 2.f * v;  zn = zZ[p] + dt * v;        }
                    else { zZ[p] = zZ[p] + (zK[p] + v) * (dt / 6.f); zn = zZ[p]; }
                    sm.Zin[sh][row][out_c] = zn;
                }
            }
        }
        __syncthreads();
    }

    // ---- in-CTA solve (Zin now holds final states) ----
    if (tid < SPC * DIM) {
        int ss = tid >> 4, cc = tid & 15;
        sm.diff[ss][cc] = sm.Zin[ss][0][cc] - sm.Zin[ss][ROWS - 1][cc];
    }
    __syncthreads();
    if ((tid & 63) == 0) {
        int ss = tid >> 6;
        float s2 = 0.f;
        #pragma unroll
        for (int i = 0; i < DIM; i++) s2 += sm.diff[ss][i] * sm.diff[ss][i];
        sm.scal[ss] = 1.f / (sqrtf(s2) + 1e-8f);
    }
    __syncthreads();

    // G[ss][jj][kk] = sum_i J[i][jj] J[i][kk],  J[i][c] = Zin[ss][c+1][i]
    for (int e = tid; e < SPC * DIM * DIM; e += NTHREADS) {
        int ss = e >> 8, idx = e & 255, jj = idx & 15, kk = idx >> 4;
        float s = 0.f;
        #pragma unroll
        for (int i = 0; i < DIM; i++) s += sm.Zin[ss][jj + 1][i] * sm.Zin[ss][kk + 1][i];
        if (jj == kk) s += 1e-6f;
        sm.G[ss][jj][kk] = s;
    }
    if (tid < SPC * DIM) {
        int ss = tid >> 4, cc = tid & 15;
        float s = 0.f;
        #pragma unroll
        for (int i = 0; i < DIM; i++) s += sm.Zin[ss][cc + 1][i] * sm.diff[ss][i];
        sm.gx[ss][cc] = s * sm.scal[ss];
    }
    __syncthreads();

    // warps 0 and 2 do the two Cholesky solves
    const int wid = tid >> 5, lane = tid & 31;
    if ((wid & 1) == 0) {
        const int ss = wid >> 1;
        float (*G)[DIM + 1] = sm.G[ss];
        for (int c = 0; c < DIM; c++) {
            if (lane == c) {
                float d = G[c][c];
                for (int k = 0; k < c; k++) d -= G[c][k] * G[c][k];
                G[c][c] = sqrtf(fmaxf(d, 1e-30f));
            }
            __syncwarp();
            if (lane > c && lane < DIM) {
                float s = G[lane][c];
                for (int k = 0; k < c; k++) s -= G[lane][k] * G[c][k];
                G[lane][c] = s / G[c][c];
            }
            __syncwarp();
        }
        if (lane < DIM) sm.wv[ss][lane] = sm.gx[ss][lane];
        __syncwarp();
        for (int c = 0; c < DIM; c++) {                 // L wv = gx
            if (lane == c) sm.wv[ss][c] = sm.wv[ss][c] / G[c][c];
            __syncwarp();
            if (lane > c && lane < DIM) sm.wv[ss][lane] -= G[lane][c] * sm.wv[ss][c];
            __syncwarp();
        }
        if (lane < DIM) sm.u[ss][lane] = sm.wv[ss][lane];
        __syncwarp();
        for (int c = DIM - 1; c >= 0; c--) {            // L^T u = wv
            if (lane == c) sm.u[ss][c] = sm.u[ss][c] / G[c][c];
            __syncwarp();
            if (lane < c) sm.u[ss][lane] -= G[c][lane] * sm.u[ss][c];
            __syncwarp();
        }
        if (lane < DIM)
            outp[(blockIdx.x * SPC + ss) * DIM + lane] = -sm.u[ss][lane];
    }
}

extern "C" void kernel_launch(void* const* d_in, const int* in_sizes, int n_in,
                              void* d_out, int out_size)
{
    Weights w;
    const float* x  = (const float*)d_in[0];
    const float* xs = (const float*)d_in[1];
    w.W0 = (const float*)d_in[2];  w.b0 = (const float*)d_in[3];
    w.W1 = (const float*)d_in[4];  w.b1 = (const float*)d_in[5];
    w.W2 = (const float*)d_in[6];  w.b2 = (const float*)d_in[7];
    w.W3 = (const float*)d_in[8];  w.b3 = (const float*)d_in[9];
    w.W4 = (const float*)d_in[10]; w.b4 = (const float*)d_in[11];
    float* out = (float*)d_out;

    flow_kernel<<<NB / SPC, NTHREADS>>>(x, xs, w, out);
}

// round 9
// speedup vs baseline: 1.1347x; 1.0059x over previous
#include <cuda_runtime.h>
#include <math.h>

#define DIM      16
#define HID      128
#define NB       1024
#define NSTEPS   10
#define ROWS     18          // row 0: primal x, rows 1..16: tangents, row 17: primal x_star
#define SPC      2           // samples per CTA
#define NTHREADS 128

struct Weights {
    const float* W0; const float* b0;
    const float* W1; const float* b1;
    const float* W2; const float* b2;
    const float* W3; const float* b3;
    const float* W4; const float* b4;
};

struct __align__(16) Smem {
    float Zin[SPC][ROWS][DIM];      // state / vel input (also final state)
    float H[SPC][2][ROWS][HID];     // hidden ping-pong per sample
    float G[SPC][DIM][DIM + 1];     // Gram / Cholesky
    float diff[SPC][DIM];
    float gx[SPC][DIM];
    float wv[SPC][DIM];
    float u[SPC][DIM];
    float scal[SPC];
};

// ---- packed fp32x2 helpers ----
__device__ __forceinline__ void ffma2(unsigned long long& d,
                                      unsigned long long a,
                                      unsigned long long b) {
    asm("fma.rn.f32x2 %0, %1, %2, %0;" : "+l"(d) : "l"(a), "l"(b));
}
__device__ __forceinline__ unsigned long long pack2(float a, float b) {
    unsigned long long r;
    asm("mov.b64 %0, {%1, %2};" : "=l"(r) : "f"(a), "f"(b));
    return r;
}
__device__ __forceinline__ float red2(unsigned long long v) {
    float lo, hi;
    asm("mov.b64 {%0, %1}, %2;" : "=f"(lo), "=f"(hi) : "l"(v));
    return lo + hi;
}
__device__ __forceinline__ float htanh(float x) {
    float y;
    asm("tanh.approx.f32 %0, %1;" : "=f"(y) : "f"(x));
    return y;
}

// ---- hidden layer 128->128: thread owns outputs {2j2, 2j2+1}, ALL 18 rows ----
__device__ __forceinline__ void hidden_layer(const float* __restrict__ W,
                                             const float* __restrict__ bb,
                                             const float (*Hin)[HID],
                                             float (*Hout)[HID], int j2)
{
    unsigned long long a0[ROWS], a1[ROWS];
    float2 bj = __ldg(reinterpret_cast<const float2*>(bb + 2 * j2));
    #pragma unroll
    for (int s = 0; s < ROWS; s++) { a0[s] = 0ull; a1[s] = 0ull; }
    a0[0]  = pack2(bj.x, 0.f); a1[0]  = pack2(bj.y, 0.f);
    a0[17] = pack2(bj.x, 0.f); a1[17] = pack2(bj.y, 0.f);

    const float* Wp = W + 2 * j2;
    // rotated pipeline: weights for i-group loaded one iteration ahead
    float2 p0 = __ldg(reinterpret_cast<const float2*>(Wp + 0 * HID));
    float2 p1 = __ldg(reinterpret_cast<const float2*>(Wp + 1 * HID));
    float2 p2 = __ldg(reinterpret_cast<const float2*>(Wp + 2 * HID));
    float2 p3 = __ldg(reinterpret_cast<const float2*>(Wp + 3 * HID));

    #pragma unroll 1
    for (int i = 0; i < HID; i += 4) {
        unsigned long long wa0 = pack2(p0.x, p1.x), wb0 = pack2(p2.x, p3.x);
        unsigned long long wa1 = pack2(p0.y, p1.y), wb1 = pack2(p2.y, p3.y);
        if (i + 4 < HID) {
            p0 = __ldg(reinterpret_cast<const float2*>(Wp + (i + 4) * HID));
            p1 = __ldg(reinterpret_cast<const float2*>(Wp + (i + 5) * HID));
            p2 = __ldg(reinterpret_cast<const float2*>(Wp + (i + 6) * HID));
            p3 = __ldg(reinterpret_cast<const float2*>(Wp + (i + 7) * HID));
        }
        #pragma unroll
        for (int s = 0; s < ROWS; s++) {
            ulonglong2 hv = *reinterpret_cast<const ulonglong2*>(&Hin[s][i]);
            ffma2(a0[s], hv.x, wa0); ffma2(a0[s], hv.y, wb0);
            ffma2(a1[s], hv.x, wa1); ffma2(a1[s], hv.y, wb1);
        }
    }

    float h00 = htanh(red2(a0[0])), h01 = htanh(red2(a1[0]));
    float g0 = 1.f - h00 * h00, g1 = 1.f - h01 * h01;
    Hout[0][2 * j2] = h00; Hout[0][2 * j2 + 1] = h01;
    #pragma unroll
    for (int s = 1; s < 17; s++) {
        Hout[s][2 * j2]     = g0 * red2(a0[s]);
        Hout[s][2 * j2 + 1] = g1 * red2(a1[s]);
    }
    Hout[17][2 * j2]     = htanh(red2(a0[17]));
    Hout[17][2 * j2 + 1] = htanh(red2(a1[17]));
}

// ---- layer 0: 16(+t) -> 128 ----
__device__ __forceinline__ void layer0(const float (*Zin)[DIM], float (*Hout)[HID],
                                       float t, const Weights& w, int j2)
{
    unsigned long long a0[ROWS], a1[ROWS];
    float2 bj = __ldg(reinterpret_cast<const float2*>(w.b0 + 2 * j2));
    float2 wt = __ldg(reinterpret_cast<const float2*>(w.W0 + DIM * HID + 2 * j2));
    float bt0 = fmaf(t, wt.x, bj.x), bt1 = fmaf(t, wt.y, bj.y);
    #pragma unroll
    for (int s = 0; s < ROWS; s++) { a0[s] = 0ull; a1[s] = 0ull; }
    a0[0]  = pack2(bt0, 0.f); a1[0]  = pack2(bt1, 0.f);
    a0[17] = pack2(bt0, 0.f); a1[17] = pack2(bt1, 0.f);

    const float* Wp = w.W0 + 2 * j2;
    #pragma unroll
    for (int i = 0; i < DIM; i += 4) {
        float2 p0 = __ldg(reinterpret_cast<const float2*>(Wp + (i + 0) * HID));
        float2 p1 = __ldg(reinterpret_cast<const float2*>(Wp + (i + 1) * HID));
        float2 p2 = __ldg(reinterpret_cast<const float2*>(Wp + (i + 2) * HID));
        float2 p3 = __ldg(reinterpret_cast<const float2*>(Wp + (i + 3) * HID));
        unsigned long long wa0 = pack2(p0.x, p1.x), wb0 = pack2(p2.x, p3.x);
        unsigned long long wa1 = pack2(p0.y, p1.y), wb1 = pack2(p2.y, p3.y);
        #pragma unroll
        for (int s = 0; s < ROWS; s++) {
            ulonglong2 hv = *reinterpret_cast<const ulonglong2*>(&Zin[s][i]);
            ffma2(a0[s], hv.x, wa0); ffma2(a0[s], hv.y, wb0);
            ffma2(a1[s], hv.x, wa1); ffma2(a1[s], hv.y, wb1);
        }
    }

    float h00 = htanh(red2(a0[0])), h01 = htanh(red2(a1[0]));
    float g0 = 1.f - h00 * h00, g1 = 1.f - h01 * h01;
    Hout[0][2 * j2] = h00; Hout[0][2 * j2 + 1] = h01;
    #pragma unroll
    for (int s = 1; s < 17; s++) {
        Hout[s][2 * j2]     = g0 * red2(a0[s]);
        Hout[s][2 * j2 + 1] = g1 * red2(a1[s]);
    }
    Hout[17][2 * j2]     = htanh(red2(a0[17]));
    Hout[17][2 * j2 + 1] = htanh(red2(a1[17]));
}

__global__ __launch_bounds__(NTHREADS, 4) void flow_kernel(
    const float* __restrict__ x, const float* __restrict__ xs, Weights w,
    float* __restrict__ outp)
{
    __shared__ Smem sm;
    const int tid = threadIdx.x;
    const int sh  = tid >> 6;          // sample within CTA
    const int j2  = tid & 63;          // output pair {2j2, 2j2+1}
    // L4/RK4 thread layout: (sh, out_c, rq) owns rows rq+4p (p<5, row<18)
    const int out_c = tid & 15, rq = (tid >> 4) & 3;

    // ---- init states ----
    for (int e = tid; e < SPC * ROWS * DIM; e += NTHREADS) {
        int ss = e / (ROWS * DIM), rr = (e / DIM) % ROWS, cc = e & 15;
        int s_idx = blockIdx.x * SPC + ss;
        float v;
        if (rr == 0)            v = x [s_idx * DIM + cc];
        else if (rr == ROWS - 1) v = xs[s_idx * DIM + cc];
        else                    v = ((rr - 1) == cc) ? 1.f : 0.f;
        sm.Zin[ss][rr][cc] = v;
    }
    __syncthreads();

    float zZ[5], zK[5];
    #pragma unroll
    for (int p = 0; p < 5; p++) {
        int row = rq + 4 * p;
        zZ[p] = (row < ROWS) ? sm.Zin[sh][row][out_c] : 0.f;
        zK[p] = 0.f;
    }

    const float dt = 1.f / NSTEPS;
    #pragma unroll 1
    for (int st = 0; st < 4 * NSTEPS; st++) {
        const int ph = st & 3;
        float t = (st >> 2) * dt;
        if (ph == 1 || ph == 2) t += 0.5f * dt;
        else if (ph == 3)       t += dt;

        layer0(sm.Zin[sh], sm.H[sh][0], t, w, j2);          __syncthreads();
        hidden_layer(w.W1, w.b1, sm.H[sh][0], sm.H[sh][1], j2); __syncthreads();
        hidden_layer(w.W2, w.b2, sm.H[sh][1], sm.H[sh][0], j2); __syncthreads();
        hidden_layer(w.W3, w.b3, sm.H[sh][0], sm.H[sh][1], j2); __syncthreads();

        // ---- layer 4 (128->16) fused with RK4 phase update; hidden in H[sh][1] ----
        {
            unsigned long long acc[5];
            #pragma unroll
            for (int p = 0; p < 5; p++) acc[p] = 0ull;
            const float* W4p = w.W4 + out_c;
            #pragma unroll 4
            for (int i = 0; i < HID; i += 4) {
                float w0 = __ldg(W4p + (i + 0) * DIM);
                float w1 = __ldg(W4p + (i + 1) * DIM);
                float w2 = __ldg(W4p + (i + 2) * DIM);
                float w3 = __ldg(W4p + (i + 3) * DIM);
                unsigned long long wa = pack2(w0, w1), wb = pack2(w2, w3);
                #pragma unroll
                for (int p = 0; p < 5; p++) {
                    int row = rq + 4 * p;
                    if (row < ROWS) {
                        ulonglong2 hv = *reinterpret_cast<const ulonglong2*>(&sm.H[sh][1][row][i]);
                        ffma2(acc[p], hv.x, wa);
                        ffma2(acc[p], hv.y, wb);
                    }
                }
            }
            float b4c = __ldg(w.b4 + out_c);
            #pragma unroll
            for (int p = 0; p < 5; p++) {
                int row = rq + 4 * p;
                if (row < ROWS) {
                    float v = red2(acc[p]);
                    if (row == 0 || row == ROWS - 1) v += b4c;
                    float zn;
                    if (ph == 0)      { zK[p]  = v;        zn = zZ[p] + 0.5f * dt * v; }
                    else if (ph == 1) { zK[p] += 2.f * v;  zn = zZ[p] + 0.5f * dt * v; }
                    else if (ph == 2) { zK[p] += 2.f * v;  zn = zZ[p] + dt * v;        }
                    else { zZ[p] = zZ[p] + (zK[p] + v) * (dt / 6.f); zn = zZ[p]; }
                    sm.Zin[sh][row][out_c] = zn;
                }
            }
        }
        __syncthreads();
    }

    // ---- in-CTA solve (Zin now holds final states) ----
    if (tid < SPC * DIM) {
        int ss = tid >> 4, cc = tid & 15;
        sm.diff[ss][cc] = sm.Zin[ss][0][cc] - sm.Zin[ss][ROWS - 1][cc];
    }
    __syncthreads();
    if ((tid & 63) == 0) {
        int ss = tid >> 6;
        float s2 = 0.f;
        #pragma unroll
        for (int i = 0; i < DIM; i++) s2 += sm.diff[ss][i] * sm.diff[ss][i];
        sm.scal[ss] = 1.f / (sqrtf(s2) + 1e-8f);
    }
    __syncthreads();

    // G[ss][jj][kk] = sum_i J[i][jj] J[i][kk],  J[i][c] = Zin[ss][c+1][i]
    for (int e = tid; e < SPC * DIM * DIM; e += NTHREADS) {
        int ss = e >> 8, idx = e & 255, jj = idx & 15, kk = idx >> 4;
        float s = 0.f;
        #pragma unroll
        for (int i = 0; i < DIM; i++) s += sm.Zin[ss][jj + 1][i] * sm.Zin[ss][kk + 1][i];
        if (jj == kk) s += 1e-6f;
        sm.G[ss][jj][kk] = s;
    }
    if (tid < SPC * DIM) {
        int ss = tid >> 4, cc = tid & 15;
        float s = 0.f;
        #pragma unroll
        for (int i = 0; i < DIM; i++) s += sm.Zin[ss][cc + 1][i] * sm.diff[ss][i];
        sm.gx[ss][cc] = s * sm.scal[ss];
    }
    __syncthreads();

    // warps 0 and 2 do the two Cholesky solves
    const int wid = tid >> 5, lane = tid & 31;
    if ((wid & 1) == 0) {
        const int ss = wid >> 1;
        float (*G)[DIM + 1] = sm.G[ss];
        for (int c = 0; c < DIM; c++) {
            if (lane == c) {
                float d = G[c][c];
                for (int k = 0; k < c; k++) d -= G[c][k] * G[c][k];
                G[c][c] = sqrtf(fmaxf(d, 1e-30f));
            }
            __syncwarp();
            if (lane > c && lane < DIM) {
                float s = G[lane][c];
                for (int k = 0; k < c; k++) s -= G[lane][k] * G[c][k];
                G[lane][c] = s / G[c][c];
            }
            __syncwarp();
        }
        if (lane < DIM) sm.wv[ss][lane] = sm.gx[ss][lane];
        __syncwarp();
        for (int c = 0; c < DIM; c++) {                 // L wv = gx
            if (lane == c) sm.wv[ss][c] = sm.wv[ss][c] / G[c][c];
            __syncwarp();
            if (lane > c && lane < DIM) sm.wv[ss][lane] -= G[lane][c] * sm.wv[ss][c];
            __syncwarp();
        }
        if (lane < DIM) sm.u[ss][lane] = sm.wv[ss][lane];
        __syncwarp();
        for (int c = DIM - 1; c >= 0; c--) {            // L^T u = wv
            if (lane == c) sm.u[ss][c] = sm.u[ss][c] / G[c][c];
            __syncwarp();
            if (lane < c) sm.u[ss][lane] -= G[c][lane] * sm.u[ss][c];
            __syncwarp();
        }
        if (lane < DIM)
            outp[(blockIdx.x * SPC + ss) * DIM + lane] = -sm.u[ss][lane];
    }
}

extern "C" void kernel_launch(void* const* d_in, const int* in_sizes, int n_in,
                              void* d_out, int out_size)
{
    Weights w;
    const float* x  = (const float*)d_in[0];
    const float* xs = (const float*)d_in[1];
    w.W0 = (const float*)d_in[2];  w.b0 = (const float*)d_in[3];
    w.W1 = (const float*)d_in[4];  w.b1 = (const float*)d_in[5];
    w.W2 = (const float*)d_in[6];  w.b2 = (const float*)d_in[7];
    w.W3 = (const float*)d_in[8];  w.b3 = (const float*)d_in[9];
    w.W4 = (const float*)d_in[10]; w.b4 = (const float*)d_in[11];
    float* out = (float*)d_out;

    flow_kernel<<<NB / SPC, NTHREADS>>>(x, xs, w, out);
}

// round 12
// speedup vs baseline: 3.4561x; 3.0458x over previous
#include <cuda_runtime.h>
#include <cuda_fp16.h>
#include <math.h>
#include <stdint.h>

#define DIM 16
#define HID 128
#define NB  1024
#define SPC 7
#define NCTAS 147
#define NT  256

// ---- SMEM layout (bytes) ----
#define O_W1H 0
#define O_W1L 32768
#define O_W2H 65536
#define O_W2L 98304
#define O_W3H 131072
#define O_W3L 163840
#define O_W0H 196608          // W0T hi: [128 n][24 k] f16, stride 48B
#define O_W0L 202752
#define O_W4H 208896          // W4T hi: [16 n][128 k] f16, swizzled 256B rows
#define O_W4L 212992
#define O_BIAS 217088         // b0..b3 [4][128] f32
#define O_TW   219136         // W0 t-row [128] f32
#define O_B4   219648         // b4 [16] f32
#define O_GBUF 219712         // g gate ping-pong [2][8][128] f32
#define SMEM_BYTES 227904

// ---- weight images in global (built by prep_kernel) ----
__device__ __align__(16) __half g_Wh[3][HID * HID];
__device__ __align__(16) __half g_Wl[3][HID * HID];
__device__ __align__(16) __half g_W0h[HID * 24];
__device__ __align__(16) __half g_W0l[HID * 24];
__device__ __align__(16) __half g_W4h[DIM * HID];
__device__ __align__(16) __half g_W4l[DIM * HID];

// ---- helpers ----
__device__ __forceinline__ uint32_t smem_u32(const void* p) {
    uint32_t a;
    asm("{ .reg .u64 t; cvta.to.shared.u64 t, %1; cvt.u32.u64 %0, t; }" : "=r"(a) : "l"(p));
    return a;
}
__device__ __forceinline__ float htanh(float v) {
    float y; asm("tanh.approx.f32 %0, %1;" : "=f"(y) : "f"(v)); return y;
}
__device__ __forceinline__ void mma16816(float* c, const uint32_t* a, uint32_t b0, uint32_t b1) {
    asm volatile("mma.sync.aligned.m16n8k16.row.col.f32.f16.f16.f32 "
        "{%0,%1,%2,%3}, {%4,%5,%6,%7}, {%8,%9}, {%0,%1,%2,%3};"
        : "+f"(c[0]), "+f"(c[1]), "+f"(c[2]), "+f"(c[3])
        : "r"(a[0]), "r"(a[1]), "r"(a[2]), "r"(a[3]), "r"(b0), "r"(b1));
}
__device__ __forceinline__ void ldsm4(uint32_t* d, uint32_t addr) {
    asm volatile("ldmatrix.sync.aligned.m8n8.x4.shared.b16 {%0,%1,%2,%3}, [%4];"
        : "=r"(d[0]), "=r"(d[1]), "=r"(d[2]), "=r"(d[3]) : "r"(addr));
}
__device__ __forceinline__ uint32_t packh2(float a, float b) {
    __half2 h = __floats2half2_rn(a, b); return *(uint32_t*)&h;
}
__device__ __forceinline__ uint32_t packl2(float a, float b) {
    __half2 h = __floats2half2_rn(a, b);
    float2 f = __half22float2(h);
    __half2 l = __floats2half2_rn(a - f.x, b - f.y);
    return *(uint32_t*)&l;
}

// ---- prep: transposed, swizzled, fp16 hi/lo weight images ----
// hidden/W4 swizzle: half-index = n*128 + (((k>>3) ^ (n&7))<<3) + (k&7)
__global__ void prep_kernel(const float* __restrict__ W0, const float* __restrict__ W1,
                            const float* __restrict__ W2, const float* __restrict__ W3,
                            const float* __restrict__ W4)
{
    int i = blockIdx.x * blockDim.x + threadIdx.x;
    if (i < 3 * HID * HID) {
        int l = i >> 14, e = i & 16383;
        int n = e >> 7, k = e & 127;
        const float* W = (l == 0) ? W1 : (l == 1) ? W2 : W3;
        float v = W[k * HID + n];
        int idx = n * 128 + (((k >> 3) ^ (n & 7)) << 3) + (k & 7);
        __half h = __float2half_rn(v);
        g_Wh[l][idx] = h;
        g_Wl[l][idx] = __float2half_rn(v - __half2float(h));
    } else if (i < 3 * HID * HID + HID * 24) {
        int e = i - 3 * HID * HID;
        int n = e / 24, k = e % 24;
        float v = (k < DIM) ? W0[k * HID + n] : 0.f;   // t-row folded into bias
        int idx = n * 24 + k;
        __half h = __float2half_rn(v);
        g_W0h[idx] = h;
        g_W0l[idx] = __float2half_rn(v - __half2float(h));
    } else if (i < 3 * HID * HID + HID * 24 + DIM * HID) {
        int e = i - 3 * HID * HID - HID * 24;
        int n = e >> 7, k = e & 127;
        float v = W4[k * DIM + n];
        int idx = n * 128 + (((k >> 3) ^ (n & 7)) << 3) + (k & 7);
        __half h = __float2half_rn(v);
        g_W4h[idx] = h;
        g_W4l[idx] = __float2half_rn(v - __half2float(h));
    }
}

__global__ void __launch_bounds__(NT) flow_kernel(
    const float* __restrict__ x, const float* __restrict__ xs,
    const float* __restrict__ b0g, const float* __restrict__ b1g,
    const float* __restrict__ b2g, const float* __restrict__ b3g,
    const float* __restrict__ b4g, const float* __restrict__ W0g,
    float* __restrict__ outp)
{
    extern __shared__ char smp[];
    const uint32_t sb = smem_u32(smp);
    const int tid = threadIdx.x, warp = tid >> 5, lane = tid & 31;
    const int q = lane & 3;
    const int r0 = warp * 16 + (lane >> 2), r1 = r0 + 8;
    const int s0 = r0 / 18, k0 = r0 - 18 * s0;
    const int s1 = r1 / 18, k1 = r1 - 18 * s1;
    const bool p0 = (k0 == 0) || (k0 == 17), p1 = (k1 == 0) || (k1 == 17);
    // ldmatrix lane geometry: c0 = matrix-row within 16-row group, half = k-16B half
    const int c0 = ((lane >> 4) << 3) + (lane & 7);
    const int half = (lane >> 3) & 1;

    // ---- stage weights + biases ----
    {
        struct { int off; const void* src; int n; } cp[10] = {
            {O_W1H, g_Wh[0], 32768}, {O_W1L, g_Wl[0], 32768},
            {O_W2H, g_Wh[1], 32768}, {O_W2L, g_Wl[1], 32768},
            {O_W3H, g_Wh[2], 32768}, {O_W3L, g_Wl[2], 32768},
            {O_W0H, g_W0h, 6144},   {O_W0L, g_W0l, 6144},
            {O_W4H, g_W4h, 4096},   {O_W4L, g_W4l, 4096} };
        #pragma unroll 1
        for (int cq = 0; cq < 10; cq++)
            for (int i = tid * 16; i < cp[cq].n; i += NT * 16)
                *(uint4*)(smp + cp[cq].off + i) = *(const uint4*)((const char*)cp[cq].src + i);
        if (tid < 128) {
            float* B = (float*)(smp + O_BIAS);
            B[tid] = __ldg(b0g + tid); B[128 + tid] = __ldg(b1g + tid);
            B[256 + tid] = __ldg(b2g + tid); B[384 + tid] = __ldg(b3g + tid);
            ((float*)(smp + O_TW))[tid] = __ldg(W0g + 16 * HID + tid);
        }
        if (tid < 16) ((float*)(smp + O_B4))[tid] = __ldg(b4g + tid);
    }
    __syncthreads();

    // ---- init RK4 state: zB/zK [row-half][cc], cc -> col {2q,2q+1,8+2q,9+2q} ----
    float zB[2][4], zK[2][4];
    #pragma unroll
    for (int rh = 0; rh < 2; rh++) {
        int row = rh ? r1 : r0;
        int ss = rh ? s1 : s0, kk = rh ? k1 : k0;
        int sidx = blockIdx.x * SPC + ss;
        #pragma unroll
        for (int cc = 0; cc < 4; cc++) {
            int c = ((cc & 2) << 2) + 2 * q + (cc & 1);
            float v = 0.f;
            if (row < 126 && sidx < NB) {
                if (kk == 0)       v = __ldg(x  + sidx * DIM + c);
                else if (kk == 17) v = __ldg(xs + sidx * DIM + c);
                else               v = ((kk - 1) == c) ? 1.f : 0.f;
            }
            zB[rh][cc] = v; zK[rh][cc] = 0.f;
        }
    }

    // L0 A fragments (K=16) from current input state
    uint32_t ah0[4], al0[4];
    ah0[0] = packh2(zB[0][0], zB[0][1]); al0[0] = packl2(zB[0][0], zB[0][1]);
    ah0[1] = packh2(zB[1][0], zB[1][1]); al0[1] = packl2(zB[1][0], zB[1][1]);
    ah0[2] = packh2(zB[0][2], zB[0][3]); al0[2] = packl2(zB[0][2], zB[0][3]);
    ah0[3] = packh2(zB[1][2], zB[1][3]); al0[3] = packl2(zB[1][2], zB[1][3]);

    float acc[16][4];
    uint32_t ah[8][4], al[8][4];

    // epilogue: bias(+t-fold) & tanh on primal rows, g-gate on tangents, pack A frags
    auto epilogue = [&](int bIdx, bool useT, float tval, int pb) {
        const float* bs  = (const float*)(smp + O_BIAS) + bIdx * 128;
        const float* twp = (const float*)(smp + O_TW);
        float* gb = (float*)(smp + O_GBUF) + pb * 1024;
        #pragma unroll
        for (int t = 0; t < 16; t++) {
            int n0 = 8 * t + 2 * q;
            if (p0) {
                float ba = bs[n0], bb = bs[n0 + 1];
                if (useT) { ba += tval * twp[n0]; bb += tval * twp[n0 + 1]; }
                float h0 = htanh(acc[t][0] + ba), h1 = htanh(acc[t][1] + bb);
                acc[t][0] = h0; acc[t][1] = h1;
                if (k0 == 0) { gb[s0 * 128 + n0] = 1.f - h0 * h0; gb[s0 * 128 + n0 + 1] = 1.f - h1 * h1; }
            }
            if (p1) {
                float ba = bs[n0], bb = bs[n0 + 1];
                if (useT) { ba += tval * twp[n0]; bb += tval * twp[n0 + 1]; }
                float h0 = htanh(acc[t][2] + ba), h1 = htanh(acc[t][3] + bb);
                acc[t][2] = h0; acc[t][3] = h1;
                if (k1 == 0) { gb[s1 * 128 + n0] = 1.f - h0 * h0; gb[s1 * 128 + n0 + 1] = 1.f - h1 * h1; }
            }
        }
        __syncthreads();
        #pragma unroll
        for (int t = 0; t < 16; t++) {
            int n0 = 8 * t + 2 * q;
            float v0 = acc[t][0], v1 = acc[t][1], v2 = acc[t][2], v3 = acc[t][3];
            if (!p0) { v0 *= gb[s0 * 128 + n0]; v1 *= gb[s0 * 128 + n0 + 1]; }
            if (!p1) { v2 *= gb[s1 * 128 + n0]; v3 *= gb[s1 * 128 + n0 + 1]; }
            int kt = t >> 1, o = (t & 1) << 1;
            ah[kt][o]     = packh2(v0, v1); al[kt][o]     = packl2(v0, v1);
            ah[kt][o + 1] = packh2(v2, v3); al[kt][o + 1] = packl2(v2, v3);
        }
    };

    const float dt = 0.1f;
    #pragma unroll 1
    for (int st = 0; st < 40; st++) {
        const int ph = st & 3;
        float tval = (st >> 2) * dt + ((ph == 1 || ph == 2) ? 0.5f * dt : (ph == 3) ? dt : 0.f);

        // ---- layer 0: K=16 ----
        #pragma unroll
        for (int t = 0; t < 16; t++)
            #pragma unroll
            for (int e = 0; e < 4; e++) acc[t][e] = 0.f;
        #pragma unroll
        for (int nt2 = 0; nt2 < 8; nt2++) {
            uint32_t wh[4], wl[4];
            uint32_t base = (nt2 * 16 + c0) * 48 + half * 16;
            ldsm4(wh, sb + O_W0H + base);
            ldsm4(wl, sb + O_W0L + base);
            mma16816(acc[2 * nt2],     ah0, wh[0], wh[1]);
            mma16816(acc[2 * nt2],     al0, wh[0], wh[1]);
            mma16816(acc[2 * nt2],     ah0, wl[0], wl[1]);
            mma16816(acc[2 * nt2 + 1], ah0, wh[2], wh[3]);
            mma16816(acc[2 * nt2 + 1], al0, wh[2], wh[3]);
            mma16816(acc[2 * nt2 + 1], ah0, wl[2], wl[3]);
        }
        epilogue(0, true, tval, 0);

        // ---- hidden layers 1..3: K=128 ----
        const int WH[3] = { O_W1H, O_W2H, O_W3H };
        const int WL[3] = { O_W1L, O_W2L, O_W3L };
        #pragma unroll 1
        for (int l = 0; l < 3; l++) {
            #pragma unroll
            for (int t = 0; t < 16; t++)
                #pragma unroll
                for (int e = 0; e < 4; e++) acc[t][e] = 0.f;
            const uint32_t bh = sb + WH[l], bl = sb + WL[l];
            #pragma unroll
            for (int kt = 0; kt < 8; kt++) {
                uint32_t xo = ((uint32_t)((2 * kt + half) ^ (c0 & 7))) << 4;
                #pragma unroll
                for (int nt2 = 0; nt2 < 8; nt2++) {
                    uint32_t wh[4], wl[4];
                    uint32_t ro = (uint32_t)(nt2 * 16 + c0) * 256 + xo;
                    ldsm4(wh, bh + ro);
                    ldsm4(wl, bl + ro);
                    mma16816(acc[2 * nt2],     ah[kt], wh[0], wh[1]);
                    mma16816(acc[2 * nt2],     al[kt], wh[0], wh[1]);
                    mma16816(acc[2 * nt2],     ah[kt], wl[0], wl[1]);
                    mma16816(acc[2 * nt2 + 1], ah[kt], wh[2], wh[3]);
                    mma16816(acc[2 * nt2 + 1], al[kt], wh[2], wh[3]);
                    mma16816(acc[2 * nt2 + 1], ah[kt], wl[2], wl[3]);
                }
            }
            epilogue(l + 1, false, 0.f, (l + 1) & 1);
        }

        // ---- layer 4: N=16 ----
        float a4[2][4];
        #pragma unroll
        for (int e = 0; e < 4; e++) { a4[0][e] = 0.f; a4[1][e] = 0.f; }
        #pragma unroll
        for (int kt = 0; kt < 8; kt++) {
            uint32_t wh[4], wl[4];
            uint32_t ro = (uint32_t)c0 * 256 + (((uint32_t)((2 * kt + half) ^ (c0 & 7))) << 4);
            ldsm4(wh, sb + O_W4H + ro);
            ldsm4(wl, sb + O_W4L + ro);
            mma16816(a4[0], ah[kt], wh[0], wh[1]);
            mma16816(a4[0], al[kt], wh[0], wh[1]);
            mma16816(a4[0], ah[kt], wl[0], wl[1]);
            mma16816(a4[1], ah[kt], wh[2], wh[3]);
            mma16816(a4[1], al[kt], wh[2], wh[3]);
            mma16816(a4[1], ah[kt], wl[2], wl[3]);
        }

        // ---- RK4 update (velocity at frag positions) ----
        {
            float v[2][4];
            v[0][0] = a4[0][0]; v[0][1] = a4[0][1]; v[1][0] = a4[0][2]; v[1][1] = a4[0][3];
            v[0][2] = a4[1][0]; v[0][3] = a4[1][1]; v[1][2] = a4[1][2]; v[1][3] = a4[1][3];
            const float* b4s = (const float*)(smp + O_B4);
            if (p0) { v[0][0] += b4s[2*q]; v[0][1] += b4s[2*q+1]; v[0][2] += b4s[8+2*q]; v[0][3] += b4s[9+2*q]; }
            if (p1) { v[1][0] += b4s[2*q]; v[1][1] += b4s[2*q+1]; v[1][2] += b4s[8+2*q]; v[1][3] += b4s[9+2*q]; }
            float zi[2][4];
            #pragma unroll
            for (int rh = 0; rh < 2; rh++)
                #pragma unroll
                for (int cc = 0; cc < 4; cc++) {
                    float vv = v[rh][cc], zn;
                    if (ph == 0)      { zK[rh][cc]  = vv;        zn = zB[rh][cc] + 0.5f * dt * vv; }
                    else if (ph == 1) { zK[rh][cc] += 2.f * vv;  zn = zB[rh][cc] + 0.5f * dt * vv; }
                    else if (ph == 2) { zK[rh][cc] += 2.f * vv;  zn = zB[rh][cc] + dt * vv; }
                    else { zB[rh][cc] += (zK[rh][cc] + vv) * (dt / 6.f); zn = zB[rh][cc]; }
                    zi[rh][cc] = zn;
                }
            ah0[0] = packh2(zi[0][0], zi[0][1]); al0[0] = packl2(zi[0][0], zi[0][1]);
            ah0[1] = packh2(zi[1][0], zi[1][1]); al0[1] = packl2(zi[1][0], zi[1][1]);
            ah0[2] = packh2(zi[0][2], zi[0][3]); al0[2] = packl2(zi[0][2], zi[0][3]);
            ah0[3] = packh2(zi[1][2], zi[1][3]); al0[3] = packl2(zi[1][2], zi[1][3]);
        }
    }

    // ---- fused solve: overlay dead weight SMEM ----
    __syncthreads();
    {
        float* Zf = (float*)(smp + O_W1H);   // [128][16]
        #pragma unroll
        for (int rh = 0; rh < 2; rh++) {
            int row = rh ? r1 : r0;
            #pragma unroll
            for (int cc = 0; cc < 4; cc++) {
                int c = ((cc & 2) << 2) + 2 * q + (cc & 1);
                Zf[row * 16 + c] = zB[rh][cc];
            }
        }
    }
    __syncthreads();

    if (warp < SPC) {
        const int ss = warp;
        const float* Zb = (const float*)(smp + O_W1H) + ss * 18 * 16;
        float* G   = (float*)(smp + O_W1L) + ss * 272;       // [16][17]
        float* dif = (float*)(smp + O_W2H) + ss * 48;
        float* wv  = dif + 16;
        float* uu  = dif + 32;

        if (lane < 16) dif[lane] = Zb[lane] - Zb[17 * 16 + lane];
        __syncwarp();
        float s2 = 0.f;
        if (lane < 16) { float d = dif[lane]; s2 = d * d; }
        #pragma unroll
        for (int o = 8; o; o >>= 1) s2 += __shfl_xor_sync(0xffffffffu, s2, o);
        float inorm = 1.f / (sqrtf(s2) + 1e-8f);

        #pragma unroll
        for (int qq = 0; qq < 8; qq++) {
            int e = lane + 32 * qq, jj = e & 15, kk = e >> 4;
            float sv = 0.f;
            #pragma unroll
            for (int i = 0; i < 16; i++) sv += Zb[(jj + 1) * 16 + i] * Zb[(kk + 1) * 16 + i];
            if (jj == kk) sv += 1e-6f;
            G[jj * 17 + kk] = sv;
        }
        if (lane < 16) {
            float sv = 0.f;
            #pragma unroll
            for (int i = 0; i < 16; i++) sv += Zb[(lane + 1) * 16 + i] * dif[i];
            wv[lane] = sv * inorm;
        }
        __syncwarp();

        for (int c = 0; c < 16; c++) {
            if (lane == c) {
                float d = G[c * 17 + c];
                for (int kq = 0; kq < c; kq++) d -= G[c * 17 + kq] * G[c * 17 + kq];
                G[c * 17 + c] = sqrtf(fmaxf(d, 1e-30f));
            }
            __syncwarp();
            if (lane > c && lane < 16) {
                float sv = G[lane * 17 + c];
                for (int kq = 0; kq < c; kq++) sv -= G[lane * 17 + kq] * G[c * 17 + kq];
                G[lane * 17 + c] = sv / G[c * 17 + c];
            }
            __syncwarp();
        }
        for (int c = 0; c < 16; c++) {
            if (lane == c) wv[c] = wv[c] / G[c * 17 + c];
            __syncwarp();
            if (lane > c && lane < 16) wv[lane] -= G[lane * 17 + c] * wv[c];
            __syncwarp();
        }
        if (lane < 16) uu[lane] = wv[lane];
        __syncwarp();
        for (int c = 15; c >= 0; c--) {
            if (lane == c) uu[c] = uu[c] / G[c * 17 + c];
            __syncwarp();
            if (lane < c) uu[lane] -= G[c * 17 + lane] * uu[c];
            __syncwarp();
        }
        int sidx = blockIdx.x * SPC + ss;
        if (lane < 16 && sidx < NB) outp[sidx * 16 + lane] = -uu[lane];
    }
}

extern "C" void kernel_launch(void* const* d_in, const int* in_sizes, int n_in,
                              void* d_out, int out_size)
{
    const float* x  = (const float*)d_in[0];
    const float* xs = (const float*)d_in[1];
    const float* W0 = (const float*)d_in[2];  const float* b0 = (const float*)d_in[3];
    const float* W1 = (const float*)d_in[4];  const float* b1 = (const float*)d_in[5];
    const float* W2 = (const float*)d_in[6];  const float* b2 = (const float*)d_in[7];
    const float* W3 = (const float*)d_in[8];  const float* b3 = (const float*)d_in[9];
    const float* W4 = (const float*)d_in[10]; const float* b4 = (const float*)d_in[11];
    float* out = (float*)d_out;

    int prep_n = 3 * HID * HID + HID * 24 + DIM * HID;
    prep_kernel<<<(prep_n + 255) / 256, 256>>>(W0, W1, W2, W3, W4);

    cudaFuncSetAttribute(flow_kernel, cudaFuncAttributeMaxDynamicSharedMemorySize, SMEM_BYTES);
    flow_kernel<<<NCTAS, NT, SMEM_BYTES>>>(x, xs, b0, b1, b2, b3, b4, W0, out);
}

// round 13
// speedup vs baseline: 3.5997x; 1.0416x over previous
#include <cuda_runtime.h>
#include <cuda_fp16.h>
#include <math.h>
#include <stdint.h>

#define DIM 16
#define HID 128
#define NB  1024
#define SPC 7
#define NCTAS 147
#define NT  256

// ---- SMEM layout (bytes) ----
#define O_W1H 0
#define O_W1L 32768
#define O_W2H 65536
#define O_W2L 98304
#define O_W3H 131072
#define O_W3L 163840
#define O_W0H 196608          // W0T hi: [128 n][24 k] f16, stride 48B
#define O_W0L 202752
#define O_W4H 208896          // W4T hi: [16 n][128 k] f16, swizzled 256B rows
#define O_W4L 212992
#define O_BIAS 217088         // b0..b3 [4][128] f32
#define O_TW   219136         // W0 t-row [128] f32
#define O_B4   219648         // b4 [16] f32
#define O_GBUF 219712         // g gate ping-pong [2][8][128] f32
#define SMEM_BYTES 227904

// ---- weight images in global (built by prep_kernel) ----
__device__ __align__(16) __half g_Wh[3][HID * HID];
__device__ __align__(16) __half g_Wl[3][HID * HID];
__device__ __align__(16) __half g_W0h[HID * 24];
__device__ __align__(16) __half g_W0l[HID * 24];
__device__ __align__(16) __half g_W4h[DIM * HID];
__device__ __align__(16) __half g_W4l[DIM * HID];

// ---- helpers ----
__device__ __forceinline__ uint32_t smem_u32(const void* p) {
    uint32_t a;
    asm("{ .reg .u64 t; cvta.to.shared.u64 t, %1; cvt.u32.u64 %0, t; }" : "=r"(a) : "l"(p));
    return a;
}
__device__ __forceinline__ float htanh(float v) {
    float y; asm("tanh.approx.f32 %0, %1;" : "=f"(y) : "f"(v)); return y;
}
__device__ __forceinline__ void mma16816(float* c, const uint32_t* a, uint32_t b0, uint32_t b1) {
    asm volatile("mma.sync.aligned.m16n8k16.row.col.f32.f16.f16.f32 "
        "{%0,%1,%2,%3}, {%4,%5,%6,%7}, {%8,%9}, {%0,%1,%2,%3};"
        : "+f"(c[0]), "+f"(c[1]), "+f"(c[2]), "+f"(c[3])
        : "r"(a[0]), "r"(a[1]), "r"(a[2]), "r"(a[3]), "r"(b0), "r"(b1));
}
__device__ __forceinline__ void ldsm4(uint32_t* d, uint32_t addr) {
    asm volatile("ldmatrix.sync.aligned.m8n8.x4.shared.b16 {%0,%1,%2,%3}, [%4];"
        : "=r"(d[0]), "=r"(d[1]), "=r"(d[2]), "=r"(d[3]) : "r"(addr));
}
__device__ __forceinline__ uint32_t packh2(float a, float b) {
    __half2 h = __floats2half2_rn(a, b); return *(uint32_t*)&h;
}
__device__ __forceinline__ uint32_t packl2(float a, float b) {
    __half2 h = __floats2half2_rn(a, b);
    float2 f = __half22float2(h);
    __half2 l = __floats2half2_rn(a - f.x, b - f.y);
    return *(uint32_t*)&l;
}

// ---- prep: transposed, swizzled, fp16 hi/lo weight images ----
// hidden/W4 swizzle: half-index = n*128 + (((k>>3) ^ (n&7))<<3) + (k&7)
__global__ void prep_kernel(const float* __restrict__ W0, const float* __restrict__ W1,
                            const float* __restrict__ W2, const float* __restrict__ W3,
                            const float* __restrict__ W4)
{
    int i = blockIdx.x * blockDim.x + threadIdx.x;
    if (i < 3 * HID * HID) {
        int l = i >> 14, e = i & 16383;
        int n = e >> 7, k = e & 127;
        const float* W = (l == 0) ? W1 : (l == 1) ? W2 : W3;
        float v = W[k * HID + n];
        int idx = n * 128 + (((k >> 3) ^ (n & 7)) << 3) + (k & 7);
        __half h = __float2half_rn(v);
        g_Wh[l][idx] = h;
        g_Wl[l][idx] = __float2half_rn(v - __half2float(h));
    } else if (i < 3 * HID * HID + HID * 24) {
        int e = i - 3 * HID * HID;
        int n = e / 24, k = e % 24;
        float v = (k < DIM) ? W0[k * HID + n] : 0.f;   // t-row folded into bias
        int idx = n * 24 + k;
        __half h = __float2half_rn(v);
        g_W0h[idx] = h;
        g_W0l[idx] = __float2half_rn(v - __half2float(h));
    } else if (i < 3 * HID * HID + HID * 24 + DIM * HID) {
        int e = i - 3 * HID * HID - HID * 24;
        int n = e >> 7, k = e & 127;
        float v = W4[k * DIM + n];
        int idx = n * 128 + (((k >> 3) ^ (n & 7)) << 3) + (k & 7);
        __half h = __float2half_rn(v);
        g_W4h[idx] = h;
        g_W4l[idx] = __float2half_rn(v - __half2float(h));
    }
}

__global__ void __launch_bounds__(NT) flow_kernel(
    const float* __restrict__ x, const float* __restrict__ xs,
    const float* __restrict__ b0g, const float* __restrict__ b1g,
    const float* __restrict__ b2g, const float* __restrict__ b3g,
    const float* __restrict__ b4g, const float* __restrict__ W0g,
    float* __restrict__ outp)
{
    extern __shared__ char smp[];
    const uint32_t sb = smem_u32(smp);
    const int tid = threadIdx.x, warp = tid >> 5, lane = tid & 31;
    const int q = lane & 3;
    const int r0 = warp * 16 + (lane >> 2), r1 = r0 + 8;
    const int s0 = r0 / 18, k0 = r0 - 18 * s0;
    const int s1 = r1 / 18, k1 = r1 - 18 * s1;
    const bool p0 = (k0 == 0) || (k0 == 17), p1 = (k1 == 0) || (k1 == 17);
    // ldmatrix lane geometry: c0 = matrix-row within 16-row group, half = k-16B half
    const int c0 = ((lane >> 4) << 3) + (lane & 7);
    const int half = (lane >> 3) & 1;

    // ---- stage weights + biases ----
    {
        struct { int off; const void* src; int n; } cp[10] = {
            {O_W1H, g_Wh[0], 32768}, {O_W1L, g_Wl[0], 32768},
            {O_W2H, g_Wh[1], 32768}, {O_W2L, g_Wl[1], 32768},
            {O_W3H, g_Wh[2], 32768}, {O_W3L, g_Wl[2], 32768},
            {O_W0H, g_W0h, 6144},   {O_W0L, g_W0l, 6144},
            {O_W4H, g_W4h, 4096},   {O_W4L, g_W4l, 4096} };
        #pragma unroll 1
        for (int cq = 0; cq < 10; cq++)
            for (int i = tid * 16; i < cp[cq].n; i += NT * 16)
                *(uint4*)(smp + cp[cq].off + i) = *(const uint4*)((const char*)cp[cq].src + i);
        if (tid < 128) {
            float* B = (float*)(smp + O_BIAS);
            B[tid] = __ldg(b0g + tid); B[128 + tid] = __ldg(b1g + tid);
            B[256 + tid] = __ldg(b2g + tid); B[384 + tid] = __ldg(b3g + tid);
            ((float*)(smp + O_TW))[tid] = __ldg(W0g + 16 * HID + tid);
        }
        if (tid < 16) ((float*)(smp + O_B4))[tid] = __ldg(b4g + tid);
    }
    __syncthreads();

    // ---- init RK4 state: zB/zK [row-half][cc], cc -> col {2q,2q+1,8+2q,9+2q} ----
    float zB[2][4], zK[2][4];
    #pragma unroll
    for (int rh = 0; rh < 2; rh++) {
        int row = rh ? r1 : r0;
        int ss = rh ? s1 : s0, kk = rh ? k1 : k0;
        int sidx = blockIdx.x * SPC + ss;
        #pragma unroll
        for (int cc = 0; cc < 4; cc++) {
            int c = ((cc & 2) << 2) + 2 * q + (cc & 1);
            float v = 0.f;
            if (row < 126 && sidx < NB) {
                if (kk == 0)       v = __ldg(x  + sidx * DIM + c);
                else if (kk == 17) v = __ldg(xs + sidx * DIM + c);
                else               v = ((kk - 1) == c) ? 1.f : 0.f;
            }
            zB[rh][cc] = v; zK[rh][cc] = 0.f;
        }
    }

    // L0 A fragments (K=16) from current input state
    uint32_t ah0[4], al0[4];
    ah0[0] = packh2(zB[0][0], zB[0][1]); al0[0] = packl2(zB[0][0], zB[0][1]);
    ah0[1] = packh2(zB[1][0], zB[1][1]); al0[1] = packl2(zB[1][0], zB[1][1]);
    ah0[2] = packh2(zB[0][2], zB[0][3]); al0[2] = packl2(zB[0][2], zB[0][3]);
    ah0[3] = packh2(zB[1][2], zB[1][3]); al0[3] = packl2(zB[1][2], zB[1][3]);

    float accA[16][4], accB[16][4];

    // primal-row epilogue on S in place: bias(+t) & tanh; write g to gb
    auto primalEpi = [&](float (&S)[16][4], int bIdx, bool useT, float tval, float* gb) {
        const float* bs  = (const float*)(smp + O_BIAS) + bIdx * 128;
        const float* twp = (const float*)(smp + O_TW);
        #pragma unroll
        for (int t = 0; t < 16; t++) {
            int n0 = 8 * t + 2 * q;
            if (p0) {
                float ba = bs[n0], bb = bs[n0 + 1];
                if (useT) { ba += tval * twp[n0]; bb += tval * twp[n0 + 1]; }
                float h0 = htanh(S[t][0] + ba), h1 = htanh(S[t][1] + bb);
                S[t][0] = h0; S[t][1] = h1;
                if (k0 == 0) { gb[s0 * 128 + n0] = 1.f - h0 * h0; gb[s0 * 128 + n0 + 1] = 1.f - h1 * h1; }
            }
            if (p1) {
                float ba = bs[n0], bb = bs[n0 + 1];
                if (useT) { ba += tval * twp[n0]; bb += tval * twp[n0 + 1]; }
                float h0 = htanh(S[t][2] + ba), h1 = htanh(S[t][3] + bb);
                S[t][2] = h0; S[t][3] = h1;
                if (k1 == 0) { gb[s1 * 128 + n0] = 1.f - h0 * h0; gb[s1 * 128 + n0 + 1] = 1.f - h1 * h1; }
            }
        }
    };

    // gated A-frag pack for k-tile kt from activations S (post primalEpi + barrier)
    auto packAB = [&](float (&S)[16][4], int kt, const float* gb, uint32_t* a_h, uint32_t* a_l) {
        #pragma unroll
        for (int u = 0; u < 2; u++) {
            int t = 2 * kt + u, n0 = 8 * t + 2 * q;
            float v0 = S[t][0], v1 = S[t][1], v2 = S[t][2], v3 = S[t][3];
            if (!p0) { v0 *= gb[s0 * 128 + n0]; v1 *= gb[s0 * 128 + n0 + 1]; }
            if (!p1) { v2 *= gb[s1 * 128 + n0]; v3 *= gb[s1 * 128 + n0 + 1]; }
            a_h[2 * u]     = packh2(v0, v1); a_l[2 * u]     = packl2(v0, v1);
            a_h[2 * u + 1] = packh2(v2, v3); a_l[2 * u + 1] = packl2(v2, v3);
        }
    };

    // hidden-layer MMA with fused per-kt gating/packing: S (acts) -> D (preacts)
    auto hiddenMMA = [&](float (&S)[16][4], float (&D)[16][4], int whOff, int wlOff,
                         const float* gb) {
        #pragma unroll
        for (int t = 0; t < 16; t++)
            #pragma unroll
            for (int e = 0; e < 4; e++) D[t][e] = 0.f;
        const uint32_t bh = sb + whOff, bl = sb + wlOff;
        #pragma unroll
        for (int kt = 0; kt < 8; kt++) {
            uint32_t a_h[4], a_l[4];
            packAB(S, kt, gb, a_h, a_l);
            uint32_t xo = ((uint32_t)((2 * kt + half) ^ (c0 & 7))) << 4;
            #pragma unroll
            for (int nt2 = 0; nt2 < 8; nt2++) {
                uint32_t wh[4], wl[4];
                uint32_t ro = (uint32_t)(nt2 * 16 + c0) * 256 + xo;
                ldsm4(wh, bh + ro);
                ldsm4(wl, bl + ro);
                mma16816(D[2 * nt2],     a_h, wh[0], wh[1]);
                mma16816(D[2 * nt2],     a_l, wh[0], wh[1]);
                mma16816(D[2 * nt2],     a_h, wl[0], wl[1]);
                mma16816(D[2 * nt2 + 1], a_h, wh[2], wh[3]);
                mma16816(D[2 * nt2 + 1], a_l, wh[2], wh[3]);
                mma16816(D[2 * nt2 + 1], a_h, wl[2], wl[3]);
            }
        }
    };

    const float dt = 0.1f;
    #pragma unroll 1
    for (int st = 0; st < 40; st++) {
        const int ph = st & 3;
        float tval = (st >> 2) * dt + ((ph == 1 || ph == 2) ? 0.5f * dt : (ph == 3) ? dt : 0.f);
        float* gb0 = (float*)(smp + O_GBUF);
        float* gb1 = gb0 + 1024;

        // ---- layer 0 MMA: K=16, A from registers (no gating) -> accA ----
        #pragma unroll
        for (int t = 0; t < 16; t++)
            #pragma unroll
            for (int e = 0; e < 4; e++) accA[t][e] = 0.f;
        #pragma unroll
        for (int nt2 = 0; nt2 < 8; nt2++) {
            uint32_t wh[4], wl[4];
            uint32_t base = (nt2 * 16 + c0) * 48 + half * 16;
            ldsm4(wh, sb + O_W0H + base);
            ldsm4(wl, sb + O_W0L + base);
            mma16816(accA[2 * nt2],     ah0, wh[0], wh[1]);
            mma16816(accA[2 * nt2],     al0, wh[0], wh[1]);
            mma16816(accA[2 * nt2],     ah0, wl[0], wl[1]);
            mma16816(accA[2 * nt2 + 1], ah0, wh[2], wh[3]);
            mma16816(accA[2 * nt2 + 1], al0, wh[2], wh[3]);
            mma16816(accA[2 * nt2 + 1], ah0, wl[2], wl[3]);
        }

        // ---- L1: epi(L0 preacts) -> gated MMA -> accB ----
        primalEpi(accA, 0, true, tval, gb0);
        __syncthreads();
        hiddenMMA(accA, accB, O_W1H, O_W1L, gb0);

        // ---- L2 ----
        primalEpi(accB, 1, false, 0.f, gb1);
        __syncthreads();
        hiddenMMA(accB, accA, O_W2H, O_W2L, gb1);

        // ---- L3 ----
        primalEpi(accA, 2, false, 0.f, gb0);
        __syncthreads();
        hiddenMMA(accA, accB, O_W3H, O_W3L, gb0);

        // ---- L4: epi(L3 preacts) -> gated MMA (N=16) ----
        primalEpi(accB, 3, false, 0.f, gb1);
        __syncthreads();
        float a4[2][4];
        #pragma unroll
        for (int e = 0; e < 4; e++) { a4[0][e] = 0.f; a4[1][e] = 0.f; }
        #pragma unroll
        for (int kt = 0; kt < 8; kt++) {
            uint32_t a_h[4], a_l[4];
            packAB(accB, kt, gb1, a_h, a_l);
            uint32_t wh[4], wl[4];
            uint32_t ro = (uint32_t)c0 * 256 + (((uint32_t)((2 * kt + half) ^ (c0 & 7))) << 4);
            ldsm4(wh, sb + O_W4H + ro);
            ldsm4(wl, sb + O_W4L + ro);
            mma16816(a4[0], a_h, wh[0], wh[1]);
            mma16816(a4[0], a_l, wh[0], wh[1]);
            mma16816(a4[0], a_h, wl[0], wl[1]);
            mma16816(a4[1], a_h, wh[2], wh[3]);
            mma16816(a4[1], a_l, wh[2], wh[3]);
            mma16816(a4[1], a_h, wl[2], wl[3]);
        }

        // ---- RK4 update (velocity at frag positions) ----
        {
            float v[2][4];
            v[0][0] = a4[0][0]; v[0][1] = a4[0][1]; v[1][0] = a4[0][2]; v[1][1] = a4[0][3];
            v[0][2] = a4[1][0]; v[0][3] = a4[1][1]; v[1][2] = a4[1][2]; v[1][3] = a4[1][3];
            const float* b4s = (const float*)(smp + O_B4);
            if (p0) { v[0][0] += b4s[2*q]; v[0][1] += b4s[2*q+1]; v[0][2] += b4s[8+2*q]; v[0][3] += b4s[9+2*q]; }
            if (p1) { v[1][0] += b4s[2*q]; v[1][1] += b4s[2*q+1]; v[1][2] += b4s[8+2*q]; v[1][3] += b4s[9+2*q]; }
            float zi[2][4];
            #pragma unroll
            for (int rh = 0; rh < 2; rh++)
                #pragma unroll
                for (int cc = 0; cc < 4; cc++) {
                    float vv = v[rh][cc], zn;
                    if (ph == 0)      { zK[rh][cc]  = vv;        zn = zB[rh][cc] + 0.5f * dt * vv; }
                    else if (ph == 1) { zK[rh][cc] += 2.f * vv;  zn = zB[rh][cc] + 0.5f * dt * vv; }
                    else if (ph == 2) { zK[rh][cc] += 2.f * vv;  zn = zB[rh][cc] + dt * vv; }
                    else { zB[rh][cc] += (zK[rh][cc] + vv) * (dt / 6.f); zn = zB[rh][cc]; }
                    zi[rh][cc] = zn;
                }
            ah0[0] = packh2(zi[0][0], zi[0][1]); al0[0] = packl2(zi[0][0], zi[0][1]);
            ah0[1] = packh2(zi[1][0], zi[1][1]); al0[1] = packl2(zi[1][0], zi[1][1]);
            ah0[2] = packh2(zi[0][2], zi[0][3]); al0[2] = packl2(zi[0][2], zi[0][3]);
            ah0[3] = packh2(zi[1][2], zi[1][3]); al0[3] = packl2(zi[1][2], zi[1][3]);
        }
    }

    // ---- fused solve: overlay dead weight SMEM ----
    __syncthreads();
    {
        float* Zf = (float*)(smp + O_W1H);   // [128][16]
        #pragma unroll
        for (int rh = 0; rh < 2; rh++) {
            int row = rh ? r1 : r0;
            #pragma unroll
            for (int cc = 0; cc < 4; cc++) {
                int c = ((cc & 2) << 2) + 2 * q + (cc & 1);
                Zf[row * 16 + c] = zB[rh][cc];
            }
        }
    }
    __syncthreads();

    if (warp < SPC) {
        const int ss = warp;
        const float* Zb = (const float*)(smp + O_W1H) + ss * 18 * 16;
        float* G   = (float*)(smp + O_W1L) + ss * 272;       // [16][17]
        float* dif = (float*)(smp + O_W2H) + ss * 48;
        float* wv  = dif + 16;
        float* uu  = dif + 32;

        if (lane < 16) dif[lane] = Zb[lane] - Zb[17 * 16 + lane];
        __syncwarp();
        float s2 = 0.f;
        if (lane < 16) { float d = dif[lane]; s2 = d * d; }
        #pragma unroll
        for (int o = 8; o; o >>= 1) s2 += __shfl_xor_sync(0xffffffffu, s2, o);
        float inorm = 1.f / (sqrtf(s2) + 1e-8f);

        #pragma unroll
        for (int qq = 0; qq < 8; qq++) {
            int e = lane + 32 * qq, jj = e & 15, kk = e >> 4;
            float sv = 0.f;
            #pragma unroll
            for (int i = 0; i < 16; i++) sv += Zb[(jj + 1) * 16 + i] * Zb[(kk + 1) * 16 + i];
            if (jj == kk) sv += 1e-6f;
            G[jj * 17 + kk] = sv;
        }
        if (lane < 16) {
            float sv = 0.f;
            #pragma unroll
            for (int i = 0; i < 16; i++) sv += Zb[(lane + 1) * 16 + i] * dif[i];
            wv[lane] = sv * inorm;
        }
        __syncwarp();

        for (int c = 0; c < 16; c++) {
            if (lane == c) {
                float d = G[c * 17 + c];
                for (int kq = 0; kq < c; kq++) d -= G[c * 17 + kq] * G[c * 17 + kq];
                G[c * 17 + c] = sqrtf(fmaxf(d, 1e-30f));
            }
            __syncwarp();
            if (lane > c && lane < 16) {
                float sv = G[lane * 17 + c];
                for (int kq = 0; kq < c; kq++) sv -= G[lane * 17 + kq] * G[c * 17 + kq];
                G[lane * 17 + c] = sv / G[c * 17 + c];
            }
            __syncwarp();
        }
        for (int c = 0; c < 16; c++) {
            if (lane == c) wv[c] = wv[c] / G[c * 17 + c];
            __syncwarp();
            if (lane > c && lane < 16) wv[lane] -= G[lane * 17 + c] * wv[c];
            __syncwarp();
        }
        if (lane < 16) uu[lane] = wv[lane];
        __syncwarp();
        for (int c = 15; c >= 0; c--) {
            if (lane == c) uu[c] = uu[c] / G[c * 17 + c];
            __syncwarp();
            if (lane < c) uu[lane] -= G[c * 17 + lane] * uu[c];
            __syncwarp();
        }
        int sidx = blockIdx.x * SPC + ss;
        if (lane < 16 && sidx < NB) outp[sidx * 16 + lane] = -uu[lane];
    }
}

extern "C" void kernel_launch(void* const* d_in, const int* in_sizes, int n_in,
                              void* d_out, int out_size)
{
    const float* x  = (const float*)d_in[0];
    const float* xs = (const float*)d_in[1];
    const float* W0 = (const float*)d_in[2];  const float* b0 = (const float*)d_in[3];
    const float* W1 = (const float*)d_in[4];  const float* b1 = (const float*)d_in[5];
    const float* W2 = (const float*)d_in[6];  const float* b2 = (const float*)d_in[7];
    const float* W3 = (const float*)d_in[8];  const float* b3 = (const float*)d_in[9];
    const float* W4 = (const float*)d_in[10]; const float* b4 = (const float*)d_in[11];
    float* out = (float*)d_out;

    int prep_n = 3 * HID * HID + HID * 24 + DIM * HID;
    prep_kernel<<<(prep_n + 255) / 256, 256>>>(W0, W1, W2, W3, W4);

    cudaFuncSetAttribute(flow_kernel, cudaFuncAttributeMaxDynamicSharedMemorySize, SMEM_BYTES);
    flow_kernel<<<NCTAS, NT, SMEM_BYTES>>>(x, xs, b0, b1, b2, b3, b4, W0, out);
}